// round 1
// baseline (speedup 1.0000x reference)
#include <cuda_runtime.h>

// Problem constants
#define TT 50176          // 2*128*196 tokens
#define DD 1024           // d_model
#define EE 2048           // d_inner
#define NS 8              // d_state
#define EPS 1e-5f

// Tiling
#define BT 128            // tokens per block
#define BE 128            // d_inner tile
#define BK 32             // k chunk
#define NTHREADS 256
#define XSTR (BT + 4)     // 132, keeps float4 alignment, breaks systematic conflicts
#define WSTR (BE + 4)

// smem layout (float offsets)
#define OFF_MU    0
#define OFF_RSTD  (OFF_MU + BT)
#define OFF_SU    (OFF_RSTD + BT)            // BT*NS = 1024
#define OFF_GAMMA (OFF_SU + BT * NS)
#define OFF_BETA  (OFF_GAMMA + DD)
#define OFF_XS    (OFF_BETA + DD)            // 2*BK*XSTR = 8448
#define OFF_WS    (OFF_XS + 2 * BK * XSTR)   // 2*BK*WSTR = 8448
#define SMEM_FLOATS (OFF_WS + 2 * BK * WSTR) // 20224 floats = 80896 bytes

__device__ __forceinline__ float silu_f(float v) {
    return v * (1.0f / (1.0f + __expf(-v)));
}

__device__ __forceinline__ void stage_ldg(const float* __restrict__ xblk,
                                          const float* __restrict__ wblk,
                                          int srow, int skh, int kc,
                                          float4 rx[4], float4 rw[4]) {
    const float4* px = reinterpret_cast<const float4*>(xblk + (size_t)srow * DD + kc * BK + skh);
    const float4* pw = reinterpret_cast<const float4*>(wblk + (size_t)srow * DD + kc * BK + skh);
#pragma unroll
    for (int u = 0; u < 4; u++) { rx[u] = px[u]; rw[u] = pw[u]; }
}

__device__ __forceinline__ void stage_sts(float* xd, float* wd,
                                          const float* s_g, const float* s_b,
                                          int srow, int skh, int kc,
                                          float mu, float rstd,
                                          const float4 rx[4], const float4 rw[4]) {
#pragma unroll
    for (int u = 0; u < 4; u++) {
        float xv[4] = {rx[u].x, rx[u].y, rx[u].z, rx[u].w};
        float wv[4] = {rw[u].x, rw[u].y, rw[u].z, rw[u].w};
#pragma unroll
        for (int c = 0; c < 4; c++) {
            int kl = skh + u * 4 + c;
            int kg = kc * BK + kl;
            // LayerNorm applied at staging time (x stays raw in gmem/L2)
            xd[kl * XSTR + srow] = fmaf((xv[c] - mu) * rstd, s_g[kg], s_b[kg]);
            wd[kl * WSTR + srow] = wv[c];
        }
    }
}

__global__ void __launch_bounds__(NTHREADS)
mamba_fused(const float* __restrict__ x,
            const float* __restrict__ Wp,    // [EE][DD]
            const float* __restrict__ bp,    // [EE]
            const float* __restrict__ Wst,   // [NS][EE]
            const float* __restrict__ bst,   // [NS]
            const float* __restrict__ Wo,    // [DD][NS]
            const float* __restrict__ bo,    // [DD]
            const float* __restrict__ istate,// [NS]
            const float* __restrict__ gamma, // [DD]
            const float* __restrict__ beta,  // [DD]
            float* __restrict__ out)
{
    extern __shared__ float sm[];
    float* s_mu   = sm + OFF_MU;
    float* s_rstd = sm + OFF_RSTD;
    float* s_su   = sm + OFF_SU;     // [BT][NS], later reused for cs
    float* s_g    = sm + OFF_GAMMA;
    float* s_b    = sm + OFF_BETA;
    float* s_xs   = sm + OFF_XS;     // [2][BK][XSTR]
    float* s_ws   = sm + OFF_WS;     // [2][BK][WSTR]

    const int tid = threadIdx.x;
    const int t0  = blockIdx.x * BT;

    // ---------------- Phase 0: LN stats + stage gamma/beta + zero su ----------------
    {
        int tk = tid >> 1, half = tid & 1;
        const float4* xr = reinterpret_cast<const float4*>(
            x + (size_t)(t0 + tk) * DD + half * (DD / 2));
        float s = 0.f, ss = 0.f;
#pragma unroll 4
        for (int i = 0; i < DD / 8; i++) {   // 128 float4 per half-row
            float4 v = xr[i];
            s  += v.x + v.y + v.z + v.w;
            ss += v.x * v.x + v.y * v.y + v.z * v.z + v.w * v.w;
        }
        s  += __shfl_xor_sync(0xFFFFFFFFu, s, 1);
        ss += __shfl_xor_sync(0xFFFFFFFFu, ss, 1);
        if (half == 0) {
            float mu  = s * (1.0f / DD);
            float var = ss * (1.0f / DD) - mu * mu;
            s_mu[tk]   = mu;
            s_rstd[tk] = rsqrtf(var + EPS);
        }
        reinterpret_cast<float4*>(s_g)[tid]  = reinterpret_cast<const float4*>(gamma)[tid];
        reinterpret_cast<float4*>(s_b)[tid]  = reinterpret_cast<const float4*>(beta)[tid];
        reinterpret_cast<float4*>(s_su)[tid] = make_float4(0.f, 0.f, 0.f, 0.f);
    }
    __syncthreads();

    // ---------------- Phase 1: proj GEMM + silu + state reduction ----------------
    const int ty   = tid >> 4;        // token group 0..15 (8 tokens each)
    const int tx   = tid & 15;        // e group 0..15 (8 e's each)
    const int srow = tid >> 1;        // staging row 0..127
    const int skh  = (tid & 1) * 16;  // staging k half-offset

    const float* xblk = x + (size_t)t0 * DD;

    for (int et = 0; et < EE / BE; et++) {
        const float* wblk = Wp + (size_t)(et * BE) * DD;
        float acc[8][8];
#pragma unroll
        for (int i = 0; i < 8; i++)
#pragma unroll
            for (int j = 0; j < 8; j++) acc[i][j] = 0.f;

        float4 rx[4], rw[4];
        const float mu_s   = s_mu[srow];
        const float rstd_s = s_rstd[srow];

        // preload + stage chunk 0 into buffer 0
        stage_ldg(xblk, wblk, srow, skh, 0, rx, rw);
        stage_sts(s_xs, s_ws, s_g, s_b, srow, skh, 0, mu_s, rstd_s, rx, rw);
        __syncthreads();

#pragma unroll 1
        for (int kc = 0; kc < DD / BK; kc++) {
            const int cur = kc & 1;
            if (kc + 1 < DD / BK)
                stage_ldg(xblk, wblk, srow, skh, kc + 1, rx, rw);

            const float* xsb = s_xs + cur * (BK * XSTR);
            const float* wsb = s_ws + cur * (BK * WSTR);
#pragma unroll 4
            for (int k = 0; k < BK; k++) {
                float4 a0 = *reinterpret_cast<const float4*>(xsb + k * XSTR + ty * 8);
                float4 a1 = *reinterpret_cast<const float4*>(xsb + k * XSTR + ty * 8 + 4);
                float4 b0 = *reinterpret_cast<const float4*>(wsb + k * WSTR + tx * 8);
                float4 b1 = *reinterpret_cast<const float4*>(wsb + k * WSTR + tx * 8 + 4);
                float a[8] = {a0.x, a0.y, a0.z, a0.w, a1.x, a1.y, a1.z, a1.w};
                float b[8] = {b0.x, b0.y, b0.z, b0.w, b1.x, b1.y, b1.z, b1.w};
#pragma unroll
                for (int i = 0; i < 8; i++)
#pragma unroll
                    for (int j = 0; j < 8; j++)
                        acc[i][j] = fmaf(a[i], b[j], acc[i][j]);
            }
            __syncthreads();
            if (kc + 1 < DD / BK) {
                stage_sts(s_xs + (1 - cur) * (BK * XSTR),
                          s_ws + (1 - cur) * (BK * WSTR),
                          s_g, s_b, srow, skh, kc + 1, mu_s, rstd_s, rx, rw);
                __syncthreads();
            }
        }

        // epilogue: bias + silu (in place), then fold into su via warp reduce
        const int ebase = et * BE + tx * 8;
        float bpv[8];
#pragma unroll
        for (int j = 0; j < 8; j++) bpv[j] = bp[ebase + j];
#pragma unroll
        for (int i = 0; i < 8; i++)
#pragma unroll
            for (int j = 0; j < 8; j++)
                acc[i][j] = silu_f(acc[i][j] + bpv[j]);

#pragma unroll
        for (int n = 0; n < NS; n++) {
            float wv[8];
#pragma unroll
            for (int j = 0; j < 8; j++) wv[j] = Wst[n * EE + ebase + j];
#pragma unroll
            for (int i = 0; i < 8; i++) {
                float r = 0.f;
#pragma unroll
                for (int j = 0; j < 8; j++) r = fmaf(acc[i][j], wv[j], r);
                // reduce across 16 tx lanes (xor 8,4,2,1 stays within 16-lane half)
                r += __shfl_xor_sync(0xFFFFFFFFu, r, 8);
                r += __shfl_xor_sync(0xFFFFFFFFu, r, 4);
                r += __shfl_xor_sync(0xFFFFFFFFu, r, 2);
                r += __shfl_xor_sync(0xFFFFFFFFu, r, 1);
                if (tx == 0)
                    s_su[(ty * 8 + i) * NS + n] += r;  // unique writer per (t,n)
            }
        }
    }
    __syncthreads();

    // ---------------- Phase 2: current_state = silu(init + b_state + su) ----------------
#pragma unroll
    for (int q = 0; q < 4; q++) {
        int idx = tid * 4 + q;                 // 0..1023 over [BT][NS]
        int n   = idx & 7;
        s_su[idx] = silu_f(s_su[idx] + bst[n] + istate[n]);
    }
    __syncthreads();

    // ---------------- Phase 3: out = x + cs @ W_outT + b_out ----------------
    const float4* x4 = reinterpret_cast<const float4*>(x + (size_t)t0 * DD);
    float4*       o4 = reinterpret_cast<float4*>(out + (size_t)t0 * DD);
    for (int idx = tid; idx < BT * (DD / 4); idx += NTHREADS) {
        int t = idx >> 8;            // DD/4 = 256 float4 per token
        int c = idx & 255;
        float4 xv  = x4[idx];
        float4 cs0 = *reinterpret_cast<const float4*>(s_su + t * NS);
        float4 cs1 = *reinterpret_cast<const float4*>(s_su + t * NS + 4);
        float xin[4] = {xv.x, xv.y, xv.z, xv.w};
        float ov[4];
        int d0 = c * 4;
#pragma unroll
        for (int dd = 0; dd < 4; dd++) {
            int d = d0 + dd;
            const float4* wo = reinterpret_cast<const float4*>(Wo + (size_t)d * NS);
            float4 w0 = wo[0], w1 = wo[1];
            float o = bo[d];
            o = fmaf(cs0.x, w0.x, o); o = fmaf(cs0.y, w0.y, o);
            o = fmaf(cs0.z, w0.z, o); o = fmaf(cs0.w, w0.w, o);
            o = fmaf(cs1.x, w1.x, o); o = fmaf(cs1.y, w1.y, o);
            o = fmaf(cs1.z, w1.z, o); o = fmaf(cs1.w, w1.w, o);
            ov[dd] = xin[dd] + o;
        }
        o4[idx] = make_float4(ov[0], ov[1], ov[2], ov[3]);
    }
}

extern "C" void kernel_launch(void* const* d_in, const int* in_sizes, int n_in,
                              void* d_out, int out_size) {
    (void)in_sizes; (void)n_in; (void)out_size;
    const float* x      = (const float*)d_in[0];
    const float* Wp     = (const float*)d_in[1];
    const float* bp     = (const float*)d_in[2];
    const float* Wst    = (const float*)d_in[3];
    const float* bst    = (const float*)d_in[4];
    const float* Wo     = (const float*)d_in[5];
    const float* bo     = (const float*)d_in[6];
    const float* istate = (const float*)d_in[7];
    const float* gamma  = (const float*)d_in[8];
    const float* beta   = (const float*)d_in[9];

    const size_t smem = SMEM_FLOATS * sizeof(float);   // 80896 B
    cudaFuncSetAttribute(mamba_fused,
                         cudaFuncAttributeMaxDynamicSharedMemorySize, (int)smem);
    mamba_fused<<<TT / BT, NTHREADS, smem>>>(x, Wp, bp, Wst, bst, Wo, bo,
                                             istate, gamma, beta, (float*)d_out);
}